// round 14
// baseline (speedup 1.0000x reference)
#include <cuda_runtime.h>
#include <math.h>
#include <stdint.h>

#define NTOT 32768
#define HTOT 32
#define D    64
#define NT   128
#define TILE_BYTES (NT * D * 4)   // 32768

// ---------- scratch (device globals: allowed; no runtime allocation) ----------
__device__ float4 g_q[NTOT * D / 4];          // 8 MB, Q in MMA C-fragment layout
__device__ float  g_logits[HTOT * NTOT];      // 4 MB

// ---------- tf32 helpers ----------
__device__ __forceinline__ uint32_t f2tf32(float f) {
    uint32_t u;
    asm("cvt.rna.tf32.f32 %0, %1;" : "=r"(u) : "f"(f));
    return u;
}

__device__ __forceinline__ void mma_tf32(float& c0, float& c1, float& c2, float& c3,
                                         uint32_t a0, uint32_t a1, uint32_t a2, uint32_t a3,
                                         uint32_t b0, uint32_t b1) {
    asm volatile(
        "mma.sync.aligned.m16n8k8.row.col.f32.tf32.tf32.f32 "
        "{%0,%1,%2,%3}, {%4,%5,%6,%7}, {%8,%9}, {%0,%1,%2,%3};"
        : "+f"(c0), "+f"(c1), "+f"(c2), "+f"(c3)
        : "r"(a0), "r"(a1), "r"(a2), "r"(a3), "r"(b0), "r"(b1));
}

__device__ __forceinline__ float poly_tanh(float x) {
    float t = x * x;
    float p = fmaf(t, -0.05396825397f, 0.13333333333f);
    p = fmaf(t, p, -0.33333333333f);
    return fmaf(x * t, p, x);
}

__device__ __forceinline__ float logscale_from_ssq(float ssq, float c) {
    float t = c * ssq;
    float p = fmaf(t, 0.22222222f, 0.28571429f);
    p = fmaf(t, p, 0.4f);
    p = fmaf(t, p, 0.66666667f);
    return fmaf(t, p, 2.0f);
}

// Fragment-native swizzled tile layout (conflict-free; rounds 3-12).
__device__ __forceinline__ int chunk_off(int token, int ci, int j) {
    int pb = (token >> 1) & 1;
    int b2 = (token >> 2) & 1;
    int jl = j & 1;
    int j1 = (j >> 1) & 1;
    int slot = ((token & 1) << 2) | (ci ^ (jl ^ pb) ^ ((j1 ^ b2) << 1));
    return ((token >> 1) << 7) | (j << 5) | (slot << 2);
}

// ---------- TMA bulk copy + mbarrier (proven rounds 7-12) ----------
__device__ __forceinline__ void mbar_init(uint32_t mbar, uint32_t cnt) {
    asm volatile("mbarrier.init.shared.b64 [%0], %1;" :: "r"(mbar), "r"(cnt) : "memory");
}
__device__ __forceinline__ void mbar_expect_tx(uint32_t mbar, uint32_t bytes) {
    asm volatile("mbarrier.arrive.expect_tx.shared.b64 _, [%0], %1;"
                 :: "r"(mbar), "r"(bytes) : "memory");
}
__device__ __forceinline__ void bulk_ld(uint32_t sdst, const void* gsrc, uint32_t mbar) {
    asm volatile(
        "cp.async.bulk.shared::cta.global.mbarrier::complete_tx::bytes [%0], [%1], %2, [%3];"
        :: "r"(sdst), "l"(gsrc), "r"((uint32_t)TILE_BYTES), "r"(mbar) : "memory");
}
__device__ __forceinline__ void mbar_wait(uint32_t mbar, uint32_t parity) {
    uint32_t done;
    asm volatile(
        "{\n\t.reg .pred p;\n\t"
        "mbarrier.try_wait.parity.acquire.cta.shared::cta.b64 p, [%1], %2;\n\t"
        "selp.b32 %0, 1, 0, p;\n\t}"
        : "=r"(done) : "r"(mbar), "r"(parity) : "memory");
    if (!done) {
        asm volatile(
            "{\n\t.reg .pred P1;\n\t"
            "WAIT_LOOP_%=:\n\t"
            "mbarrier.try_wait.parity.acquire.cta.shared::cta.b64 P1, [%0], %1, 0x989680;\n\t"
            "@P1 bra.uni WAIT_DONE_%=;\n\t"
            "bra.uni WAIT_LOOP_%=;\n\t"
            "WAIT_DONE_%=:\n\t}"
            :: "r"(mbar), "r"(parity) : "memory");
    }
}

// 512-thread permute-only transform (R12)
__device__ __forceinline__ void transform_tile512(const float* __restrict__ stag,
                                                  uint32_t* __restrict__ tileU,
                                                  int pt) {
    const float4* s4 = reinterpret_cast<const float4*>(stag);
    const int col4 = pt & 15;
    const int rgrp = pt >> 4;         // 0..31
    const int j    = col4 >> 2;
    const int posR = col4 & 3;
    const int posP = posR ^ ((j & 1) << 1);
    int base[4];
    #pragma unroll
    for (int ci = 0; ci < 4; ci++)
        base[ci] = chunk_off(rgrp, ci, j) + posP;
    #pragma unroll
    for (int jj = 0; jj < 4; jj++) {
        float4 v = s4[pt + 512 * jj];
        int o = jj << 11;
        tileU[base[0] + o] = f2tf32(v.x);
        tileU[base[1] + o] = f2tf32(v.y);
        tileU[base[2] + o] = f2tf32(v.z);
        tileU[base[3] + o] = f2tf32(v.w);
    }
}

// 256-thread permute-only transform (R9 pattern)
__device__ __forceinline__ void transform_tile256(const float* __restrict__ stag,
                                                  uint32_t* __restrict__ tileU,
                                                  int pt) {
    const float4* s4 = reinterpret_cast<const float4*>(stag);
    const int col4 = pt & 15;
    const int rgrp = pt >> 4;         // 0..15
    const int j    = col4 >> 2;
    const int posR = col4 & 3;
    const int posP = posR ^ ((j & 1) << 1);
    int base[4];
    #pragma unroll
    for (int ci = 0; ci < 4; ci++)
        base[ci] = chunk_off(rgrp, ci, j) + posP;
    #pragma unroll
    for (int jj = 0; jj < 8; jj++) {
        float4 v = s4[pt + 256 * jj];
        int o = jj << 10;
        tileU[base[0] + o] = f2tf32(v.x);
        tileU[base[1] + o] = f2tf32(v.y);
        tileU[base[2] + o] = f2tf32(v.z);
        tileU[base[3] + o] = f2tf32(v.w);
    }
}

// 512-thread norm pass (R12): token = t>>2, d-quarter t&3
__device__ __forceinline__ void norm_pass512(const float* __restrict__ stag,
                                             float* __restrict__ scaleS,
                                             int t, float c) {
    const float4* s4 = reinterpret_cast<const float4*>(stag);
    const int token = t >> 2;
    const int dq    = t & 3;
    float ssq = 0.f;
    #pragma unroll
    for (int k = 0; k < 4; k++) {
        float4 v = s4[token * 16 + dq * 4 + k];
        ssq = fmaf(v.x, v.x, fmaf(v.y, v.y, fmaf(v.z, v.z, fmaf(v.w, v.w, ssq))));
    }
    ssq += __shfl_xor_sync(0xffffffffu, ssq, 1);
    ssq += __shfl_xor_sync(0xffffffffu, ssq, 2);
    if (dq == 0) scaleS[token] = logscale_from_ssq(ssq, c);
}

// 256-thread norm pass: token = t>>1, d-half t&1
__device__ __forceinline__ void norm_pass256(const float* __restrict__ stag,
                                             float* __restrict__ scaleS,
                                             int t, float c) {
    const float4* s4 = reinterpret_cast<const float4*>(stag);
    const int token = t >> 1;
    const int dh    = t & 1;
    float ssq = 0.f;
    #pragma unroll
    for (int k = 0; k < 8; k++) {
        float4 v = s4[token * 16 + dh * 8 + k];
        ssq = fmaf(v.x, v.x, fmaf(v.y, v.y, fmaf(v.z, v.z, fmaf(v.w, v.w, ssq))));
    }
    ssq += __shfl_xor_sync(0xffffffffu, ssq, 1);
    if (dh == 0) scaleS[token] = logscale_from_ssq(ssq, c);
}

// ============ kernel 0: Q = scale*(cur @ Wq^T) + bq + bk, C-frag layout ============
__global__ __launch_bounds__(512, 1)
void q_kernel(const float* __restrict__ cur,
              const float* __restrict__ curv,
              const float* __restrict__ Wq,
              const float* __restrict__ bq,
              const float* __restrict__ bk) {
    extern __shared__ float sm[];
    uint32_t* tileU = reinterpret_cast<uint32_t*>(sm);   // 8192 u32
    float* stag   = sm + 8192;                           // 8192
    float* scaleS = sm + 16384;                          // 128
    uint32_t mbar = (uint32_t)__cvta_generic_to_shared(sm + 16512);

    const int t    = threadIdx.x;
    const int lane = t & 31;
    const int w    = t >> 5;
    const int n0   = blockIdx.x * NT;
    const float c  = curv[0];

    const int eq = w & 3, tq = w >> 2;
    const int Tq = tq * 32;
    const int lr = lane >> 2, ci = lane & 3;
    const int er0 = eq * 16 + lr;

    int fb[4];
    #pragma unroll
    for (int j = 0; j < 4; j++) fb[j] = chunk_off(Tq + lr, ci, j);

    if (t == 0) {
        mbar_init(mbar, 1);
        asm volatile("fence.proxy.async.shared::cta;" ::: "memory");
        mbar_expect_tx(mbar, TILE_BYTES);
        bulk_ld((uint32_t)__cvta_generic_to_shared(stag), cur + (size_t)n0 * D, mbar);
    }

    uint32_t A[8][4];
    #pragma unroll
    for (int kc = 0; kc < 8; kc++) {
        A[kc][0] = f2tf32(Wq[er0 * 64 + kc * 8 + ci]);
        A[kc][1] = f2tf32(Wq[(er0 + 8) * 64 + kc * 8 + ci]);
        A[kc][2] = f2tf32(Wq[er0 * 64 + kc * 8 + ci + 4]);
        A[kc][3] = f2tf32(Wq[(er0 + 8) * 64 + kc * 8 + ci + 4]);
    }
    const float bias0 = bq[er0]     + bk[er0];
    const float bias1 = bq[er0 + 8] + bk[er0 + 8];

    __syncthreads();
    if (lane == 0) { mbar_wait(mbar, 0); }
    __syncthreads();
    norm_pass512(stag, scaleS, t, c);
    transform_tile512(stag, tileU, t);
    __syncthreads();

    #pragma unroll
    for (int nc = 0; nc < 4; nc++) {
        float c0 = 0.f, c1 = 0.f, c2 = 0.f, c3 = 0.f;
        #pragma unroll
        for (int j = 0; j < 4; j++) {
            uint4 q = *reinterpret_cast<const uint4*>(&tileU[fb[j] + nc * 512]);
            if ((j & 1) == 0) {
                mma_tf32(c0,c1,c2,c3, A[2*j][0],A[2*j][1],A[2*j][2],A[2*j][3], q.x, q.y);
                mma_tf32(c0,c1,c2,c3, A[2*j+1][0],A[2*j+1][1],A[2*j+1][2],A[2*j+1][3], q.z, q.w);
            } else {
                mma_tf32(c0,c1,c2,c3, A[2*j][0],A[2*j][1],A[2*j][2],A[2*j][3], q.z, q.w);
                mma_tf32(c0,c1,c2,c3, A[2*j+1][0],A[2*j+1][1],A[2*j+1][2],A[2*j+1][3], q.x, q.y);
            }
        }
        int T0 = Tq + nc * 8;
        float s0 = scaleS[T0 + 2 * ci];
        float s1 = scaleS[T0 + 2 * ci + 1];
        float4 q4;
        q4.x = fmaf(s0, c0, bias0);
        q4.y = fmaf(s1, c1, bias0);
        q4.z = fmaf(s0, c2, bias1);
        q4.w = fmaf(s1, c3, bias1);
        g_q[blockIdx.x * 2048 + eq * 512 + (tq * 4 + nc) * 32 + lane] = q4;
    }
}

// ============ kernel 1: logits[h, n] (one (tile, h) per CTA) ============
__global__ __launch_bounds__(256, 3)
void logit_kernel(const float* __restrict__ hist,
                  const float* __restrict__ curv,
                  const float* __restrict__ Wk,
                  const float* __restrict__ av) {
    extern __shared__ float sm[];
    uint32_t* tileU = reinterpret_cast<uint32_t*>(sm);   // 8192 u32
    float* stag   = sm + 8192;                           // 8192
    float* scaleS = sm + 16384;                          // 128
    float* lp     = sm + 16512;                          // 512
    uint32_t mbar = (uint32_t)__cvta_generic_to_shared(sm + 17024);

    const int tile = blockIdx.x;
    const int h    = blockIdx.y;
    const int n0   = tile * NT;
    const int t    = threadIdx.x;
    const int lane = t & 31;
    const int w    = t >> 5;          // 0..7
    const float c  = curv[0];

    const int eq = w & 3, tq = w >> 2;   // tq in {0,1}
    const int Tq = tq * 64;
    const int lr = lane >> 2, ci = lane & 3;
    const int er0 = eq * 16 + lr;

    int fb[4];
    #pragma unroll
    for (int j = 0; j < 4; j++) fb[j] = chunk_off(Tq + lr, ci, j);

    if (t == 0) {
        mbar_init(mbar, 1);
        asm volatile("fence.proxy.async.shared::cta;" ::: "memory");
        mbar_expect_tx(mbar, TILE_BYTES);
        bulk_ld((uint32_t)__cvta_generic_to_shared(stag),
                hist + ((size_t)h * NTOT + n0) * D, mbar);
    }

    uint32_t A[8][4];
    #pragma unroll
    for (int kc = 0; kc < 8; kc++) {
        A[kc][0] = f2tf32(Wk[er0 * 64 + kc * 8 + ci]);
        A[kc][1] = f2tf32(Wk[(er0 + 8) * 64 + kc * 8 + ci]);
        A[kc][2] = f2tf32(Wk[er0 * 64 + kc * 8 + ci + 4]);
        A[kc][3] = f2tf32(Wk[(er0 + 8) * 64 + kc * 8 + ci + 4]);
    }
    const float av0 = av[er0];
    const float av1 = av[er0 + 8];

    __syncthreads();
    if (lane == 0) { mbar_wait(mbar, 0); }
    __syncthreads();
    norm_pass256(stag, scaleS, t, c);
    transform_tile256(stag, tileU, t);
    __syncthreads();

    #pragma unroll
    for (int nc = 0; nc < 8; nc++) {
        float4 qf = g_q[tile * 2048 + eq * 512 + (tq * 8 + nc) * 32 + lane];
        float c0 = 0.f, c1 = 0.f, c2 = 0.f, c3 = 0.f;
        #pragma unroll
        for (int j = 0; j < 4; j++) {
            uint4 q = *reinterpret_cast<const uint4*>(&tileU[fb[j] + nc * 512]);
            if ((j & 1) == 0) {
                mma_tf32(c0,c1,c2,c3, A[2*j][0],A[2*j][1],A[2*j][2],A[2*j][3], q.x, q.y);
                mma_tf32(c0,c1,c2,c3, A[2*j+1][0],A[2*j+1][1],A[2*j+1][2],A[2*j+1][3], q.z, q.w);
            } else {
                mma_tf32(c0,c1,c2,c3, A[2*j][0],A[2*j][1],A[2*j][2],A[2*j][3], q.z, q.w);
                mma_tf32(c0,c1,c2,c3, A[2*j+1][0],A[2*j+1][1],A[2*j+1][2],A[2*j+1][3], q.x, q.y);
            }
        }
        int T0 = Tq + nc * 8;
        float s0 = scaleS[T0 + 2 * ci];
        float s1 = scaleS[T0 + 2 * ci + 1];
        float t0 = poly_tanh(fmaf(s0, c0, qf.x));
        float t1 = poly_tanh(fmaf(s1, c1, qf.y));
        float t2 = poly_tanh(fmaf(s0, c2, qf.z));
        float t3 = poly_tanh(fmaf(s1, c3, qf.w));
        float p0 = fmaf(t0, av0, t2 * av1);
        float p1 = fmaf(t1, av0, t3 * av1);
        #pragma unroll
        for (int off = 4; off < 32; off <<= 1) {
            p0 += __shfl_xor_sync(0xffffffffu, p0, off);
            p1 += __shfl_xor_sync(0xffffffffu, p1, off);
        }
        if (lane < 4) {
            float2 st; st.x = p0; st.y = p1;
            *reinterpret_cast<float2*>(&lp[eq * 128 + T0 + 2 * lane]) = st;
        }
    }
    __syncthreads();

    if (t < 128)
        g_logits[(size_t)h * NTOT + n0 + t] =
            lp[t] + lp[128 + t] + lp[256 + t] + lp[384 + t];
}

// ============ kernel 2: softmax over h + weighted sum + exp map ============
__global__ __launch_bounds__(512, 2)
void out_kernel(const float* __restrict__ hist,
                const float* __restrict__ curv,
                float* __restrict__ out) {
    __shared__ float lgS[HTOT * 132];   // padded stride vs bank conflicts
    __shared__ float denS[NT];

    const int n0 = blockIdx.x * NT;
    const int t  = threadIdx.x;
    const int tok = t >> 2;
    const int dq  = t & 3;
    const float c = curv[0];

    // exp(logits) -> smem (coalesced global reads)
    for (int i = t; i < HTOT * NT; i += 512) {
        int hh = i >> 7, n = i & 127;
        lgS[hh * 132 + n] = __expf(g_logits[(size_t)hh * NTOT + n0 + n]);
    }
    __syncthreads();
    if (t < NT) {
        float s = 0.f;
        #pragma unroll
        for (int hh = 0; hh < HTOT; hh++) s += lgS[hh * 132 + t];
        denS[t] = s;
    }
    __syncthreads();

    float acc[16];
    #pragma unroll
    for (int k = 0; k < 16; k++) acc[k] = 0.f;

    const float* base = hist + ((size_t)(n0 + tok)) * D + dq * 16;

    #pragma unroll 2
    for (int hh = 0; hh < HTOT; hh++) {
        const float4* hp = reinterpret_cast<const float4*>(base + (size_t)hh * NTOT * D);
        float4 v0 = hp[0], v1 = hp[1], v2 = hp[2], v3 = hp[3];
        float ssq = 0.f;
        ssq = fmaf(v0.x, v0.x, fmaf(v0.y, v0.y, fmaf(v0.z, v0.z, fmaf(v0.w, v0.w, ssq))));
        ssq = fmaf(v1.x, v1.x, fmaf(v1.y, v1.y, fmaf(v1.z, v1.z, fmaf(v1.w, v1.w, ssq))));
        ssq = fmaf(v2.x, v2.x, fmaf(v2.y, v2.y, fmaf(v2.z, v2.z, fmaf(v2.w, v2.w, ssq))));
        ssq = fmaf(v3.x, v3.x, fmaf(v3.y, v3.y, fmaf(v3.z, v3.z, fmaf(v3.w, v3.w, ssq))));
        ssq += __shfl_xor_sync(0xffffffffu, ssq, 1);
        ssq += __shfl_xor_sync(0xffffffffu, ssq, 2);
        float scale = logscale_from_ssq(ssq, c);
        float pw = lgS[hh * 132 + tok] * scale;
        acc[0]  = fmaf(pw, v0.x, acc[0]);  acc[1]  = fmaf(pw, v0.y, acc[1]);
        acc[2]  = fmaf(pw, v0.z, acc[2]);  acc[3]  = fmaf(pw, v0.w, acc[3]);
        acc[4]  = fmaf(pw, v1.x, acc[4]);  acc[5]  = fmaf(pw, v1.y, acc[5]);
        acc[6]  = fmaf(pw, v1.z, acc[6]);  acc[7]  = fmaf(pw, v1.w, acc[7]);
        acc[8]  = fmaf(pw, v2.x, acc[8]);  acc[9]  = fmaf(pw, v2.y, acc[9]);
        acc[10] = fmaf(pw, v2.z, acc[10]); acc[11] = fmaf(pw, v2.w, acc[11]);
        acc[12] = fmaf(pw, v3.x, acc[12]); acc[13] = fmaf(pw, v3.y, acc[13]);
        acc[14] = fmaf(pw, v3.z, acc[14]); acc[15] = fmaf(pw, v3.w, acc[15]);
    }

    // epilogue: ws = acc/den ; context = tanh(sc*|ws|/2)/(sc*|ws|) * ws
    float sinv = __fdividef(1.f, denS[tok]);
    float ssq = 0.f;
    #pragma unroll
    for (int k = 0; k < 16; k++) ssq = fmaf(acc[k], acc[k], ssq);
    ssq += __shfl_xor_sync(0xffffffffu, ssq, 1);
    ssq += __shfl_xor_sync(0xffffffffu, ssq, 2);

    float sc = sqrtf(c);
    float r = sqrtf(ssq) * sinv;
    float u = sc * r;
    float g;
    if (u > 1e-12f) {
        float e = __expf(u);
        g = __fdividef(e - 1.f, (e + 1.f) * u);    // tanh(u/2)/u
    } else {
        g = 0.5f;
    }
    float f = g * sinv;

    float4* op = reinterpret_cast<float4*>(out + ((size_t)(n0 + tok)) * D + dq * 16);
    #pragma unroll
    for (int k = 0; k < 4; k++) {
        float4 o;
        o.x = acc[4*k]   * f;
        o.y = acc[4*k+1] * f;
        o.z = acc[4*k+2] * f;
        o.w = acc[4*k+3] * f;
        op[k] = o;
    }
}

extern "C" void kernel_launch(void* const* d_in, const int* in_sizes, int n_in,
                              void* d_out, int out_size) {
    const float* cur  = (const float*)d_in[0];
    const float* hist = (const float*)d_in[1];
    const float* curv = (const float*)d_in[2];
    const float* Wq   = (const float*)d_in[3];
    const float* bq   = (const float*)d_in[4];
    const float* Wk   = (const float*)d_in[5];
    const float* bk   = (const float*)d_in[6];
    const float* av   = (const float*)d_in[7];
    float* o = (float*)d_out;

    const int smem_q = (16512 + 8) * sizeof(float);
    const int smem_l = (17024 + 8) * sizeof(float);
    cudaFuncSetAttribute(q_kernel, cudaFuncAttributeMaxDynamicSharedMemorySize, smem_q);
    cudaFuncSetAttribute(logit_kernel, cudaFuncAttributeMaxDynamicSharedMemorySize, smem_l);

    q_kernel<<<NTOT / NT, 512, smem_q>>>(cur, curv, Wq, bq, bk);
    dim3 g1(NTOT / NT, HTOT);
    logit_kernel<<<g1, 256, smem_l>>>(hist, curv, Wk, av);
    out_kernel<<<NTOT / NT, 512>>>(hist, curv, o);
}

// round 15
// speedup vs baseline: 1.7710x; 1.7710x over previous
#include <cuda_runtime.h>
#include <math.h>
#include <stdint.h>

#define NTOT 32768
#define HTOT 32
#define D    64
#define NT   64
#define NTHREADS 256
#define TILE_BYTES (NT * D * 4)   // 16384

// ---------- tf32 helpers ----------
__device__ __forceinline__ uint32_t f2tf32(float f) {
    uint32_t u;
    asm("cvt.rna.tf32.f32 %0, %1;" : "=r"(u) : "f"(f));
    return u;
}

__device__ __forceinline__ void mma_tf32(float& c0, float& c1, float& c2, float& c3,
                                         uint32_t a0, uint32_t a1, uint32_t a2, uint32_t a3,
                                         uint32_t b0, uint32_t b1) {
    asm volatile(
        "mma.sync.aligned.m16n8k8.row.col.f32.tf32.tf32.f32 "
        "{%0,%1,%2,%3}, {%4,%5,%6,%7}, {%8,%9}, {%0,%1,%2,%3};"
        : "+f"(c0), "+f"(c1), "+f"(c2), "+f"(c3)
        : "r"(a0), "r"(a1), "r"(a2), "r"(a3), "r"(b0), "r"(b1));
}

__device__ __forceinline__ float poly_tanh(float x) {
    float t = x * x;
    float p = fmaf(t, -0.05396825397f, 0.13333333333f);
    p = fmaf(t, p, -0.33333333333f);
    return fmaf(x * t, p, x);
}

__device__ __forceinline__ float logscale_from_ssq(float ssq, float c) {
    float t = c * ssq;
    float p = fmaf(t, 0.22222222f, 0.28571429f);
    p = fmaf(t, p, 0.4f);
    p = fmaf(t, p, 0.66666667f);
    return fmaf(t, p, 2.0f);
}

// Fragment-native swizzled tile layout (conflict-free; rounds 3-13).
__device__ __forceinline__ int chunk_off(int token, int ci, int j) {
    int pb = (token >> 1) & 1;
    int b2 = (token >> 2) & 1;
    int jl = j & 1;
    int j1 = (j >> 1) & 1;
    int slot = ((token & 1) << 2) | (ci ^ (jl ^ pb) ^ ((j1 ^ b2) << 1));
    return ((token >> 1) << 7) | (j << 5) | (slot << 2);
}

// ---------- TMA bulk copy + mbarrier (proven rounds 7-13) ----------
__device__ __forceinline__ void mbar_init(uint32_t mbar, uint32_t cnt) {
    asm volatile("mbarrier.init.shared.b64 [%0], %1;" :: "r"(mbar), "r"(cnt) : "memory");
}
__device__ __forceinline__ void mbar_expect_tx(uint32_t mbar, uint32_t bytes) {
    asm volatile("mbarrier.arrive.expect_tx.shared.b64 _, [%0], %1;"
                 :: "r"(mbar), "r"(bytes) : "memory");
}
__device__ __forceinline__ void bulk_ld(uint32_t sdst, const void* gsrc, uint32_t mbar) {
    asm volatile(
        "cp.async.bulk.shared::cta.global.mbarrier::complete_tx::bytes [%0], [%1], %2, [%3];"
        :: "r"(sdst), "l"(gsrc), "r"((uint32_t)TILE_BYTES), "r"(mbar) : "memory");
}
__device__ __forceinline__ void mbar_wait(uint32_t mbar, uint32_t parity) {
    uint32_t done;
    asm volatile(
        "{\n\t.reg .pred p;\n\t"
        "mbarrier.try_wait.parity.acquire.cta.shared::cta.b64 p, [%1], %2;\n\t"
        "selp.b32 %0, 1, 0, p;\n\t}"
        : "=r"(done) : "r"(mbar), "r"(parity) : "memory");
    if (!done) {
        asm volatile(
            "{\n\t.reg .pred P1;\n\t"
            "WAIT_LOOP_%=:\n\t"
            "mbarrier.try_wait.parity.acquire.cta.shared::cta.b64 P1, [%0], %1, 0x989680;\n\t"
            "@P1 bra.uni WAIT_DONE_%=;\n\t"
            "bra.uni WAIT_LOOP_%=;\n\t"
            "WAIT_DONE_%=:\n\t}"
            :: "r"(mbar), "r"(parity) : "memory");
    }
}

// 256-thread transform for a 64x64 tile with per-row log-map scale (R7 pattern):
// thread handles rows rgrp + 16*jj (jj=0..3); norms via 16-lane shfl.
__device__ __forceinline__ void transform_tile(const float* __restrict__ stag,
                                               uint32_t* __restrict__ tileU,
                                               int t, float c) {
    const float4* s4 = reinterpret_cast<const float4*>(stag);
    const int col4 = t & 15;
    const int rgrp = t >> 4;          // 0..15
    const int j    = col4 >> 2;
    const int posR = col4 & 3;
    const int posP = posR ^ ((j & 1) << 1);
    int base[4];
    #pragma unroll
    for (int ci = 0; ci < 4; ci++)
        base[ci] = chunk_off(rgrp, ci, j) + posP;

    float4 v[4];
    float  ss[4];
    #pragma unroll
    for (int jj = 0; jj < 4; jj++) v[jj] = s4[t + 256 * jj];
    #pragma unroll
    for (int jj = 0; jj < 4; jj++) {
        float s = fmaf(v[jj].x, v[jj].x, fmaf(v[jj].y, v[jj].y,
                  fmaf(v[jj].z, v[jj].z, v[jj].w * v[jj].w)));
        #pragma unroll
        for (int off = 1; off < 16; off <<= 1)
            s += __shfl_xor_sync(0xffffffffu, s, off);
        ss[jj] = s;
    }
    #pragma unroll
    for (int jj = 0; jj < 4; jj++) {
        float sc = logscale_from_ssq(ss[jj], c);
        int o = jj << 10;             // +16 rows = +1024 floats
        tileU[base[0] + o] = f2tf32(v[jj].x * sc);
        tileU[base[1] + o] = f2tf32(v[jj].y * sc);
        tileU[base[2] + o] = f2tf32(v[jj].z * sc);
        tileU[base[3] + o] = f2tf32(v[jj].w * sc);
    }
}

__global__ __launch_bounds__(NTHREADS, 2)
void hyp_attn_kernel(const float* __restrict__ cur,
                     const float* __restrict__ hist,
                     const float* __restrict__ curv,
                     const float* __restrict__ Wq,
                     const float* __restrict__ bq,
                     const float* __restrict__ Wk,
                     const float* __restrict__ bk,
                     const float* __restrict__ av,
                     float* __restrict__ out) {
    extern __shared__ float sm[];
    uint32_t* tileU = reinterpret_cast<uint32_t*>(sm);   // 4096 u32
    float* stagA = sm + 4096;                            // 4096
    float* stagB = sm + 8192;                            // 4096
    float* lp    = sm + 12288;                           // 256
    uint32_t mbarBase = (uint32_t)__cvta_generic_to_shared(sm + 12544);

    const int t    = threadIdx.x;
    const int lane = t & 31;
    const int w    = t >> 5;          // 0..7
    const int n0   = blockIdx.x * NT;
    const float c  = curv[0];

    const uint32_t mbar0 = mbarBase;
    const uint32_t mbar1 = mbarBase + 8;
    const uint32_t stAu = (uint32_t)__cvta_generic_to_shared(stagA);
    const uint32_t stBu = (uint32_t)__cvta_generic_to_shared(stagB);

    // warp roles: e-quarter (w&3)*16, token half (w>>2)*32
    const int eq = w & 3;
    const int th = w >> 2;
    const int lr = lane >> 2;
    const int ci = lane & 3;
    const int Tq = th * 32;
    const int r0 = eq * 16 + lr;

    int fb[4];
    #pragma unroll
    for (int j = 0; j < 4; j++) fb[j] = chunk_off(Tq + lr, ci, j);

    // RMW / epilogue ownership: token = t>>2 (0..63), d-quarter dq = t&3
    const int tok = t >> 2;
    const int dq  = t & 3;
    int roff[4];
    #pragma unroll
    for (int cc = 0; cc < 4; cc++) roff[cc] = chunk_off(tok, cc, dq);

    const float bias0 = bq[r0]     + bk[r0];
    const float bias1 = bq[r0 + 8] + bk[r0 + 8];
    const float av0   = av[r0];
    const float av1   = av[r0 + 8];

    // ---- mbarrier init + first TMA load (current tile) ----
    if (t == 0) {
        mbar_init(mbar0, 1);
        mbar_init(mbar1, 1);
        asm volatile("fence.proxy.async.shared::cta;" ::: "memory");
        mbar_expect_tx(mbar0, TILE_BYTES);
        bulk_ld(stAu, cur + (size_t)n0 * D, mbar0);
    }

    // ---- A fragments (Wq first) while the load flies ----
    uint32_t A[8][4];
    #pragma unroll
    for (int kc = 0; kc < 8; kc++) {
        A[kc][0] = f2tf32(Wq[r0 * 64 + kc * 8 + ci]);
        A[kc][1] = f2tf32(Wq[(r0 + 8) * 64 + kc * 8 + ci]);
        A[kc][2] = f2tf32(Wq[r0 * 64 + kc * 8 + ci + 4]);
        A[kc][3] = f2tf32(Wq[(r0 + 8) * 64 + kc * 8 + ci + 4]);
    }

    __syncthreads();                  // mbarrier init visible
    if (lane == 0) { mbar_wait(mbar0, 0); }
    __syncthreads();                  // cur staging visible CTA-wide
    transform_tile(stagA, tileU, t, c);
    __syncthreads();                  // tileU (cur) ready; stagA free

    // prefetch history h=0 (stagA) and h=1 (stagB)
    if (t == 0) {
        mbar_expect_tx(mbar0, TILE_BYTES);
        bulk_ld(stAu, hist + (size_t)n0 * D, mbar0);
        mbar_expect_tx(mbar1, TILE_BYTES);
        bulk_ld(stBu, hist + ((size_t)NTOT + n0) * D, mbar1);
    }

    // ---- Q fragments (kept in registers) ----
    float qf[4][4];
    #pragma unroll
    for (int nc = 0; nc < 4; nc++) {
        uint4 q[4];
        #pragma unroll
        for (int j = 0; j < 4; j++)
            q[j] = *reinterpret_cast<const uint4*>(&tileU[fb[j] + nc * 512]);
        float c0 = 0.f, c1 = 0.f, c2 = 0.f, c3 = 0.f;
        mma_tf32(c0,c1,c2,c3, A[0][0],A[0][1],A[0][2],A[0][3], q[0].x, q[0].y);
        mma_tf32(c0,c1,c2,c3, A[1][0],A[1][1],A[1][2],A[1][3], q[0].z, q[0].w);
        mma_tf32(c0,c1,c2,c3, A[2][0],A[2][1],A[2][2],A[2][3], q[1].z, q[1].w);
        mma_tf32(c0,c1,c2,c3, A[3][0],A[3][1],A[3][2],A[3][3], q[1].x, q[1].y);
        mma_tf32(c0,c1,c2,c3, A[4][0],A[4][1],A[4][2],A[4][3], q[2].x, q[2].y);
        mma_tf32(c0,c1,c2,c3, A[5][0],A[5][1],A[5][2],A[5][3], q[2].z, q[2].w);
        mma_tf32(c0,c1,c2,c3, A[6][0],A[6][1],A[6][2],A[6][3], q[3].z, q[3].w);
        mma_tf32(c0,c1,c2,c3, A[7][0],A[7][1],A[7][2],A[7][3], q[3].x, q[3].y);
        qf[nc][0] = c0 + bias0;
        qf[nc][1] = c1 + bias0;
        qf[nc][2] = c2 + bias1;
        qf[nc][3] = c3 + bias1;
    }

    // ---- swap A fragments to Wk ----
    #pragma unroll
    for (int kc = 0; kc < 8; kc++) {
        A[kc][0] = f2tf32(Wk[r0 * 64 + kc * 8 + ci]);
        A[kc][1] = f2tf32(Wk[(r0 + 8) * 64 + kc * 8 + ci]);
        A[kc][2] = f2tf32(Wk[r0 * 64 + kc * 8 + ci + 4]);
        A[kc][3] = f2tf32(Wk[(r0 + 8) * 64 + kc * 8 + ci + 4]);
    }

    float accR[4][4];
    #pragma unroll
    for (int cc = 0; cc < 4; cc++)
        #pragma unroll
        for (int p = 0; p < 4; p++) accR[cc][p] = 0.f;
    float sreg = 0.f;
    int ph0 = 1, ph1 = 0;

    for (int h = 0; h < HTOT; h++) {
        if (lane == 0) {
            if (h & 1) { mbar_wait(mbar1, ph1); } else { mbar_wait(mbar0, ph0); }
        }
        if (h & 1) ph1 ^= 1; else ph0 ^= 1;
        __syncthreads();              // staging visible; prev RMW done with tileU
        transform_tile((h & 1) ? stagB : stagA, tileU, t, c);
        __syncthreads();              // tileU ready; staging consumed

        // TMA load for h+2 into the buffer just freed
        if (h + 2 < HTOT && t == 0) {
            uint32_t mb   = (h & 1) ? mbar1 : mbar0;
            uint32_t sdst = (h & 1) ? stBu : stAu;
            mbar_expect_tx(mb, TILE_BYTES);
            bulk_ld(sdst, hist + ((size_t)(h + 2) * NTOT + n0) * D, mb);
        }

        // K MMA fused with tanh-logit partials
        #pragma unroll
        for (int nc = 0; nc < 4; nc++) {
            uint4 q[4];
            #pragma unroll
            for (int j = 0; j < 4; j++)
                q[j] = *reinterpret_cast<const uint4*>(&tileU[fb[j] + nc * 512]);
            float c0 = 0.f, c1 = 0.f, c2 = 0.f, c3 = 0.f;
            mma_tf32(c0,c1,c2,c3, A[0][0],A[0][1],A[0][2],A[0][3], q[0].x, q[0].y);
            mma_tf32(c0,c1,c2,c3, A[1][0],A[1][1],A[1][2],A[1][3], q[0].z, q[0].w);
            mma_tf32(c0,c1,c2,c3, A[2][0],A[2][1],A[2][2],A[2][3], q[1].z, q[1].w);
            mma_tf32(c0,c1,c2,c3, A[3][0],A[3][1],A[3][2],A[3][3], q[1].x, q[1].y);
            mma_tf32(c0,c1,c2,c3, A[4][0],A[4][1],A[4][2],A[4][3], q[2].x, q[2].y);
            mma_tf32(c0,c1,c2,c3, A[5][0],A[5][1],A[5][2],A[5][3], q[2].z, q[2].w);
            mma_tf32(c0,c1,c2,c3, A[6][0],A[6][1],A[6][2],A[6][3], q[3].z, q[3].w);
            mma_tf32(c0,c1,c2,c3, A[7][0],A[7][1],A[7][2],A[7][3], q[3].x, q[3].y);
            float t0 = poly_tanh(qf[nc][0] + c0);
            float t1 = poly_tanh(qf[nc][1] + c1);
            float t2 = poly_tanh(qf[nc][2] + c2);
            float t3 = poly_tanh(qf[nc][3] + c3);
            float p0 = fmaf(t0, av0, t2 * av1);
            float p1 = fmaf(t1, av0, t3 * av1);
            #pragma unroll
            for (int off = 4; off < 32; off <<= 1) {
                p0 += __shfl_xor_sync(0xffffffffu, p0, off);
                p1 += __shfl_xor_sync(0xffffffffu, p1, off);
            }
            if (lane < 4) {
                float2 st; st.x = p0; st.y = p1;
                *reinterpret_cast<float2*>(&lp[eq * 64 + Tq + nc * 8 + 2 * lane]) = st;
            }
        }
        __syncthreads();              // logit partials ready

        // softmax accumulation + register RMW (tileU valid until next transform)
        float L  = lp[tok] + lp[64 + tok] + lp[128 + tok] + lp[192 + tok];
        float pe = __expf(L);         // logits bounded << 88
        sreg += pe;
        #pragma unroll
        for (int cc = 0; cc < 4; cc++) {
            float4 t4 = *reinterpret_cast<const float4*>(&tileU[roff[cc]]);
            accR[cc][0] = fmaf(pe, t4.x, accR[cc][0]);
            accR[cc][1] = fmaf(pe, t4.y, accR[cc][1]);
            accR[cc][2] = fmaf(pe, t4.z, accR[cc][2]);
            accR[cc][3] = fmaf(pe, t4.w, accR[cc][3]);
        }
    }

    // ---- epilogue: ws = acc/s ; context = tanh(sc*|ws|/2)/(sc*|ws|) * ws ----
    float sinv = __fdividef(1.f, sreg);
    float ssq = 0.f;
    #pragma unroll
    for (int cc = 0; cc < 4; cc++)
        #pragma unroll
        for (int p = 0; p < 4; p++)
            ssq = fmaf(accR[cc][p], accR[cc][p], ssq);
    // combine the 4 d-quarters (4 consecutive lanes own one token)
    ssq += __shfl_xor_sync(0xffffffffu, ssq, 1);
    ssq += __shfl_xor_sync(0xffffffffu, ssq, 2);

    float sc = sqrtf(c);
    float r = sqrtf(ssq) * sinv;
    float u = sc * r;
    float g;
    if (u > 1e-12f) {
        float e = __expf(u);
        g = __fdividef(e - 1.f, (e + 1.f) * u);    // tanh(u/2)/u
    } else {
        g = 0.5f;
    }
    float f = g * sinv;

    const int xo = (dq & 1) << 1;     // posP = posR ^ ((j&1)<<1)
    float4* op = reinterpret_cast<float4*>(out + (size_t)(n0 + tok) * D + dq * 16);
    #pragma unroll
    for (int gi = 0; gi < 4; gi++) {
        int pos = gi ^ xo;
        float4 o;
        o.x = accR[0][pos] * f;
        o.y = accR[1][pos] * f;
        o.z = accR[2][pos] * f;
        o.w = accR[3][pos] * f;
        op[gi] = o;
    }
}

extern "C" void kernel_launch(void* const* d_in, const int* in_sizes, int n_in,
                              void* d_out, int out_size) {
    const float* cur  = (const float*)d_in[0];
    const float* hist = (const float*)d_in[1];
    const float* curv = (const float*)d_in[2];
    const float* Wq   = (const float*)d_in[3];
    const float* bq   = (const float*)d_in[4];
    const float* Wk   = (const float*)d_in[5];
    const float* bk   = (const float*)d_in[6];
    const float* av   = (const float*)d_in[7];
    float* o = (float*)d_out;

    const int smem_bytes = (12544 + 8) * sizeof(float);   // ~49 KB -> 2 CTAs/SM
    cudaFuncSetAttribute(hyp_attn_kernel,
                         cudaFuncAttributeMaxDynamicSharedMemorySize, smem_bytes);
    hyp_attn_kernel<<<NTOT / NT, NTHREADS, smem_bytes>>>(
        cur, hist, curv, Wq, bq, Wk, bk, av, o);
}

// round 16
// speedup vs baseline: 1.8517x; 1.0456x over previous
#include <cuda_runtime.h>
#include <math.h>
#include <stdint.h>

#define NTOT 32768
#define HTOT 32
#define D    64
#define NT   64
#define NTHREADS 256
#define TILE_BYTES (NT * D * 4)   // 16384

// ---------- tf32 helpers ----------
__device__ __forceinline__ uint32_t f2tf32(float f) {
    uint32_t u;
    asm("cvt.rna.tf32.f32 %0, %1;" : "=r"(u) : "f"(f));
    return u;
}

__device__ __forceinline__ void mma_tf32(float& c0, float& c1, float& c2, float& c3,
                                         uint32_t a0, uint32_t a1, uint32_t a2, uint32_t a3,
                                         uint32_t b0, uint32_t b1) {
    asm volatile(
        "mma.sync.aligned.m16n8k8.row.col.f32.tf32.tf32.f32 "
        "{%0,%1,%2,%3}, {%4,%5,%6,%7}, {%8,%9}, {%0,%1,%2,%3};"
        : "+f"(c0), "+f"(c1), "+f"(c2), "+f"(c3)
        : "r"(a0), "r"(a1), "r"(a2), "r"(a3), "r"(b0), "r"(b1));
}

__device__ __forceinline__ float poly_tanh(float x) {
    float t = x * x;
    float p = fmaf(t, -0.05396825397f, 0.13333333333f);
    p = fmaf(t, p, -0.33333333333f);
    return fmaf(x * t, p, x);
}

__device__ __forceinline__ float logscale_from_ssq(float ssq, float c) {
    float t = c * ssq;
    float p = fmaf(t, 0.22222222f, 0.28571429f);
    p = fmaf(t, p, 0.4f);
    p = fmaf(t, p, 0.66666667f);
    return fmaf(t, p, 2.0f);
}

// Fragment-native swizzled tile layout (conflict-free; rounds 3-14).
__device__ __forceinline__ int chunk_off(int token, int ci, int j) {
    int pb = (token >> 1) & 1;
    int b2 = (token >> 2) & 1;
    int jl = j & 1;
    int j1 = (j >> 1) & 1;
    int slot = ((token & 1) << 2) | (ci ^ (jl ^ pb) ^ ((j1 ^ b2) << 1));
    return ((token >> 1) << 7) | (j << 5) | (slot << 2);
}

// ---------- TMA bulk copy + mbarrier (proven rounds 7-14) ----------
__device__ __forceinline__ void mbar_init(uint32_t mbar, uint32_t cnt) {
    asm volatile("mbarrier.init.shared.b64 [%0], %1;" :: "r"(mbar), "r"(cnt) : "memory");
}
__device__ __forceinline__ void mbar_expect_tx(uint32_t mbar, uint32_t bytes) {
    asm volatile("mbarrier.arrive.expect_tx.shared.b64 _, [%0], %1;"
                 :: "r"(mbar), "r"(bytes) : "memory");
}
__device__ __forceinline__ void bulk_ld(uint32_t sdst, const void* gsrc, uint32_t mbar) {
    asm volatile(
        "cp.async.bulk.shared::cta.global.mbarrier::complete_tx::bytes [%0], [%1], %2, [%3];"
        :: "r"(sdst), "l"(gsrc), "r"((uint32_t)TILE_BYTES), "r"(mbar) : "memory");
}
__device__ __forceinline__ void mbar_wait(uint32_t mbar, uint32_t parity) {
    uint32_t done;
    asm volatile(
        "{\n\t.reg .pred p;\n\t"
        "mbarrier.try_wait.parity.acquire.cta.shared::cta.b64 p, [%1], %2;\n\t"
        "selp.b32 %0, 1, 0, p;\n\t}"
        : "=r"(done) : "r"(mbar), "r"(parity) : "memory");
    if (!done) {
        asm volatile(
            "{\n\t.reg .pred P1;\n\t"
            "WAIT_LOOP_%=:\n\t"
            "mbarrier.try_wait.parity.acquire.cta.shared::cta.b64 P1, [%0], %1, 0x989680;\n\t"
            "@P1 bra.uni WAIT_DONE_%=;\n\t"
            "bra.uni WAIT_LOOP_%=;\n\t"
            "WAIT_DONE_%=:\n\t}"
            :: "r"(mbar), "r"(parity) : "memory");
    }
}

// 256-thread transform for a 64x64 tile with per-row log-map scale (R14):
// thread handles rows rgrp + 16*jj (jj=0..3); norms via 16-lane shfl.
__device__ __forceinline__ void transform_tile(const float* __restrict__ stag,
                                               uint32_t* __restrict__ tileU,
                                               int t, float c) {
    const float4* s4 = reinterpret_cast<const float4*>(stag);
    const int col4 = t & 15;
    const int rgrp = t >> 4;          // 0..15
    const int j    = col4 >> 2;
    const int posR = col4 & 3;
    const int posP = posR ^ ((j & 1) << 1);
    int base[4];
    #pragma unroll
    for (int ci = 0; ci < 4; ci++)
        base[ci] = chunk_off(rgrp, ci, j) + posP;

    float4 v[4];
    float  ss[4];
    #pragma unroll
    for (int jj = 0; jj < 4; jj++) v[jj] = s4[t + 256 * jj];
    #pragma unroll
    for (int jj = 0; jj < 4; jj++) {
        float s = fmaf(v[jj].x, v[jj].x, fmaf(v[jj].y, v[jj].y,
                  fmaf(v[jj].z, v[jj].z, v[jj].w * v[jj].w)));
        #pragma unroll
        for (int off = 1; off < 16; off <<= 1)
            s += __shfl_xor_sync(0xffffffffu, s, off);
        ss[jj] = s;
    }
    #pragma unroll
    for (int jj = 0; jj < 4; jj++) {
        float sc = logscale_from_ssq(ss[jj], c);
        int o = jj << 10;             // +16 rows = +1024 floats
        tileU[base[0] + o] = f2tf32(v[jj].x * sc);
        tileU[base[1] + o] = f2tf32(v[jj].y * sc);
        tileU[base[2] + o] = f2tf32(v[jj].z * sc);
        tileU[base[3] + o] = f2tf32(v[jj].w * sc);
    }
}

__global__ __launch_bounds__(NTHREADS, 2)
void hyp_attn_kernel(const float* __restrict__ cur,
                     const float* __restrict__ hist,
                     const float* __restrict__ curv,
                     const float* __restrict__ Wq,
                     const float* __restrict__ bq,
                     const float* __restrict__ Wk,
                     const float* __restrict__ bk,
                     const float* __restrict__ av,
                     float* __restrict__ out) {
    extern __shared__ float sm[];
    uint32_t* tile0 = reinterpret_cast<uint32_t*>(sm);        // 4096 u32
    uint32_t* tile1 = reinterpret_cast<uint32_t*>(sm) + 4096; // 4096 u32
    float* stagA = sm + 8192;                                 // 4096
    float* stagB = sm + 12288;                                // 4096
    float* lp    = sm + 16384;                                // 256
    uint32_t mbarBase = (uint32_t)__cvta_generic_to_shared(sm + 16640);

    const int t    = threadIdx.x;
    const int lane = t & 31;
    const int w    = t >> 5;          // 0..7
    const int n0   = blockIdx.x * NT;
    const float c  = curv[0];

    const uint32_t mbar0 = mbarBase;
    const uint32_t mbar1 = mbarBase + 8;
    const uint32_t stAu = (uint32_t)__cvta_generic_to_shared(stagA);
    const uint32_t stBu = (uint32_t)__cvta_generic_to_shared(stagB);

    // warp roles: e-quarter (w&3)*16, token half (w>>2)*32
    const int eq = w & 3;
    const int th = w >> 2;
    const int lr = lane >> 2;
    const int ci = lane & 3;
    const int Tq = th * 32;
    const int r0 = eq * 16 + lr;

    int fb[4];
    #pragma unroll
    for (int j = 0; j < 4; j++) fb[j] = chunk_off(Tq + lr, ci, j);

    // RMW / epilogue ownership: token = t>>2 (0..63), d-quarter dq = t&3
    const int tok = t >> 2;
    const int dq  = t & 3;
    int roff[4];
    #pragma unroll
    for (int cc = 0; cc < 4; cc++) roff[cc] = chunk_off(tok, cc, dq);

    const float bias0 = bq[r0]     + bk[r0];
    const float bias1 = bq[r0 + 8] + bk[r0 + 8];
    const float av0   = av[r0];
    const float av1   = av[r0 + 8];

    // ---- mbarrier init + first TMA load (current tile) ----
    if (t == 0) {
        mbar_init(mbar0, 1);
        mbar_init(mbar1, 1);
        asm volatile("fence.proxy.async.shared::cta;" ::: "memory");
        mbar_expect_tx(mbar0, TILE_BYTES);
        bulk_ld(stAu, cur + (size_t)n0 * D, mbar0);
    }

    // ---- A fragments (Wq first) while the load flies ----
    uint32_t A[8][4];
    #pragma unroll
    for (int kc = 0; kc < 8; kc++) {
        A[kc][0] = f2tf32(Wq[r0 * 64 + kc * 8 + ci]);
        A[kc][1] = f2tf32(Wq[(r0 + 8) * 64 + kc * 8 + ci]);
        A[kc][2] = f2tf32(Wq[r0 * 64 + kc * 8 + ci + 4]);
        A[kc][3] = f2tf32(Wq[(r0 + 8) * 64 + kc * 8 + ci + 4]);
    }

    __syncthreads();                  // mbarrier init visible to all
    mbar_wait(mbar0, 0);              // per-thread acquire: cur staging visible
    transform_tile(stagA, tile1, t, c);   // cur -> tile1 (loop uses tile[h&1])
    __syncthreads();                  // tile1 ready; stagA fully consumed

    // prefetch history h=0 (stagA) and h=1 (stagB)
    if (t == 0) {
        mbar_expect_tx(mbar0, TILE_BYTES);
        bulk_ld(stAu, hist + (size_t)n0 * D, mbar0);
        mbar_expect_tx(mbar1, TILE_BYTES);
        bulk_ld(stBu, hist + ((size_t)NTOT + n0) * D, mbar1);
    }

    // ---- Q fragments from tile1 (kept in registers) ----
    float qf[4][4];
    #pragma unroll
    for (int nc = 0; nc < 4; nc++) {
        uint4 q[4];
        #pragma unroll
        for (int j = 0; j < 4; j++)
            q[j] = *reinterpret_cast<const uint4*>(&tile1[fb[j] + nc * 512]);
        float c0 = 0.f, c1 = 0.f, c2 = 0.f, c3 = 0.f;
        mma_tf32(c0,c1,c2,c3, A[0][0],A[0][1],A[0][2],A[0][3], q[0].x, q[0].y);
        mma_tf32(c0,c1,c2,c3, A[1][0],A[1][1],A[1][2],A[1][3], q[0].z, q[0].w);
        mma_tf32(c0,c1,c2,c3, A[2][0],A[2][1],A[2][2],A[2][3], q[1].z, q[1].w);
        mma_tf32(c0,c1,c2,c3, A[3][0],A[3][1],A[3][2],A[3][3], q[1].x, q[1].y);
        mma_tf32(c0,c1,c2,c3, A[4][0],A[4][1],A[4][2],A[4][3], q[2].x, q[2].y);
        mma_tf32(c0,c1,c2,c3, A[5][0],A[5][1],A[5][2],A[5][3], q[2].z, q[2].w);
        mma_tf32(c0,c1,c2,c3, A[6][0],A[6][1],A[6][2],A[6][3], q[3].z, q[3].w);
        mma_tf32(c0,c1,c2,c3, A[7][0],A[7][1],A[7][2],A[7][3], q[3].x, q[3].y);
        qf[nc][0] = c0 + bias0;
        qf[nc][1] = c1 + bias0;
        qf[nc][2] = c2 + bias1;
        qf[nc][3] = c3 + bias1;
    }
    // NOTE: tile1 is not overwritten until h=1's transform, which is ordered
    // after h=0's two __syncthreads — all Q reads retire before then.

    // ---- swap A fragments to Wk ----
    #pragma unroll
    for (int kc = 0; kc < 8; kc++) {
        A[kc][0] = f2tf32(Wk[r0 * 64 + kc * 8 + ci]);
        A[kc][1] = f2tf32(Wk[(r0 + 8) * 64 + kc * 8 + ci]);
        A[kc][2] = f2tf32(Wk[r0 * 64 + kc * 8 + ci + 4]);
        A[kc][3] = f2tf32(Wk[(r0 + 8) * 64 + kc * 8 + ci + 4]);
    }

    float accR[4][4];
    #pragma unroll
    for (int cc = 0; cc < 4; cc++)
        #pragma unroll
        for (int p = 0; p < 4; p++) accR[cc][p] = 0.f;
    float sreg = 0.f;
    int ph0 = 1, ph1 = 0;

    for (int h = 0; h < HTOT; h++) {
        // per-thread acquire wait on this h's staging buffer (no CTA barrier)
        if (h & 1) { mbar_wait(mbar1, ph1); ph1 ^= 1; }
        else       { mbar_wait(mbar0, ph0); ph0 ^= 1; }

        uint32_t* tU = (h & 1) ? tile1 : tile0;
        transform_tile((h & 1) ? stagB : stagA, tU, t, c);
        __syncthreads();              // B1: tile[h&1] ready; staging consumed

        // TMA load for h+2 into the staging buffer just freed
        if (h + 2 < HTOT && t == 0) {
            uint32_t mb   = (h & 1) ? mbar1 : mbar0;
            uint32_t sdst = (h & 1) ? stBu : stAu;
            mbar_expect_tx(mb, TILE_BYTES);
            bulk_ld(sdst, hist + ((size_t)(h + 2) * NTOT + n0) * D, mb);
        }

        // K MMA fused with tanh-logit partials
        #pragma unroll
        for (int nc = 0; nc < 4; nc++) {
            uint4 q[4];
            #pragma unroll
            for (int j = 0; j < 4; j++)
                q[j] = *reinterpret_cast<const uint4*>(&tU[fb[j] + nc * 512]);
            float c0 = 0.f, c1 = 0.f, c2 = 0.f, c3 = 0.f;
            mma_tf32(c0,c1,c2,c3, A[0][0],A[0][1],A[0][2],A[0][3], q[0].x, q[0].y);
            mma_tf32(c0,c1,c2,c3, A[1][0],A[1][1],A[1][2],A[1][3], q[0].z, q[0].w);
            mma_tf32(c0,c1,c2,c3, A[2][0],A[2][1],A[2][2],A[2][3], q[1].z, q[1].w);
            mma_tf32(c0,c1,c2,c3, A[3][0],A[3][1],A[3][2],A[3][3], q[1].x, q[1].y);
            mma_tf32(c0,c1,c2,c3, A[4][0],A[4][1],A[4][2],A[4][3], q[2].x, q[2].y);
            mma_tf32(c0,c1,c2,c3, A[5][0],A[5][1],A[5][2],A[5][3], q[2].z, q[2].w);
            mma_tf32(c0,c1,c2,c3, A[6][0],A[6][1],A[6][2],A[6][3], q[3].z, q[3].w);
            mma_tf32(c0,c1,c2,c3, A[7][0],A[7][1],A[7][2],A[7][3], q[3].x, q[3].y);
            float t0 = poly_tanh(qf[nc][0] + c0);
            float t1 = poly_tanh(qf[nc][1] + c1);
            float t2 = poly_tanh(qf[nc][2] + c2);
            float t3 = poly_tanh(qf[nc][3] + c3);
            float p0 = fmaf(t0, av0, t2 * av1);
            float p1 = fmaf(t1, av0, t3 * av1);
            #pragma unroll
            for (int off = 4; off < 32; off <<= 1) {
                p0 += __shfl_xor_sync(0xffffffffu, p0, off);
                p1 += __shfl_xor_sync(0xffffffffu, p1, off);
            }
            if (lane < 4) {
                float2 st; st.x = p0; st.y = p1;
                *reinterpret_cast<float2*>(&lp[eq * 64 + Tq + nc * 8 + 2 * lane]) = st;
            }
        }
        __syncthreads();              // B2: logit partials ready

        // softmax accumulation + register RMW.
        // tile[h&1] stays valid: the next write to it is transform h+2,
        // which is ordered behind B1(h+1) -> all RMW reads here retire first.
        // lp is protected by B1(h+1) the same way.
        float L  = lp[tok] + lp[64 + tok] + lp[128 + tok] + lp[192 + tok];
        float pe = __expf(L);         // logits bounded << 88
        sreg += pe;
        #pragma unroll
        for (int cc = 0; cc < 4; cc++) {
            float4 t4 = *reinterpret_cast<const float4*>(&tU[roff[cc]]);
            accR[cc][0] = fmaf(pe, t4.x, accR[cc][0]);
            accR[cc][1] = fmaf(pe, t4.y, accR[cc][1]);
            accR[cc][2] = fmaf(pe, t4.z, accR[cc][2]);
            accR[cc][3] = fmaf(pe, t4.w, accR[cc][3]);
        }
    }

    // ---- epilogue: ws = acc/s ; context = tanh(sc*|ws|/2)/(sc*|ws|) * ws ----
    float sinv = __fdividef(1.f, sreg);
    float ssq = 0.f;
    #pragma unroll
    for (int cc = 0; cc < 4; cc++)
        #pragma unroll
        for (int p = 0; p < 4; p++)
            ssq = fmaf(accR[cc][p], accR[cc][p], ssq);
    // combine the 4 d-quarters (4 consecutive lanes own one token)
    ssq += __shfl_xor_sync(0xffffffffu, ssq, 1);
    ssq += __shfl_xor_sync(0xffffffffu, ssq, 2);

    float sc = sqrtf(c);
    float r = sqrtf(ssq) * sinv;
    float u = sc * r;
    float g;
    if (u > 1e-12f) {
        float e = __expf(u);
        g = __fdividef(e - 1.f, (e + 1.f) * u);    // tanh(u/2)/u
    } else {
        g = 0.5f;
    }
    float f = g * sinv;

    const int xo = (dq & 1) << 1;     // posP = posR ^ ((j&1)<<1)
    float4* op = reinterpret_cast<float4*>(out + (size_t)(n0 + tok) * D + dq * 16);
    #pragma unroll
    for (int gi = 0; gi < 4; gi++) {
        int pos = gi ^ xo;
        float4 o;
        o.x = accR[0][pos] * f;
        o.y = accR[1][pos] * f;
        o.z = accR[2][pos] * f;
        o.w = accR[3][pos] * f;
        op[gi] = o;
    }
}

extern "C" void kernel_launch(void* const* d_in, const int* in_sizes, int n_in,
                              void* d_out, int out_size) {
    const float* cur  = (const float*)d_in[0];
    const float* hist = (const float*)d_in[1];
    const float* curv = (const float*)d_in[2];
    const float* Wq   = (const float*)d_in[3];
    const float* bq   = (const float*)d_in[4];
    const float* Wk   = (const float*)d_in[5];
    const float* bk   = (const float*)d_in[6];
    const float* av   = (const float*)d_in[7];
    float* o = (float*)d_out;

    const int smem_bytes = (16640 + 8) * sizeof(float);   // ~67 KB -> 2 CTAs/SM
    cudaFuncSetAttribute(hyp_attn_kernel,
                         cudaFuncAttributeMaxDynamicSharedMemorySize, smem_bytes);
    hyp_attn_kernel<<<NTOT / NT, NTHREADS, smem_bytes>>>(
        cur, hist, curv, Wq, bq, Wk, bk, av, o);
}